// round 4
// baseline (speedup 1.0000x reference)
#include <cuda_runtime.h>
#include <cuda_fp16.h>
#include <cstdint>

// Problem constants
#define BATCH 8
#define TT    4096
#define DIM   512
#define NH    8
#define HD    64
#define QDIM  512
#define GG    3584
#define NCHUNK 56          // GG / 64

// Packed hi/lo fp16 scratch (u32 = hi in bits[15:0], lo in bits[31:16])
__device__ __align__(256) uint32_t g_Q[(size_t)NH*BATCH*QDIM*HD];
__device__ __align__(256) uint32_t g_K[(size_t)NH*BATCH*GG*HD];
__device__ __align__(256) uint32_t g_V[(size_t)NH*BATCH*GG*HD];
__device__ __align__(256) uint32_t g_Hd[(size_t)BATCH*QDIM*NH*HD];

__device__ __forceinline__ uint32_t packsplit(float v) {
    __half h = __float2half_rn(v);
    __half l = __float2half_rn(v - __half2float(h));
    return (uint32_t)__half_as_ushort(h) | ((uint32_t)__half_as_ushort(l) << 16);
}
__device__ __forceinline__ void psplit2(float p0, float p1, uint32_t& hi, uint32_t& lo) {
    __half2 h = __floats2half2_rn(p0, p1);
    float2 hf = __half22float2(h);
    __half2 l = __floats2half2_rn(p0 - hf.x, p1 - hf.y);
    hi = *reinterpret_cast<uint32_t*>(&h);
    lo = *reinterpret_cast<uint32_t*>(&l);
}
__device__ __forceinline__ uint32_t h2scale8(uint32_t a) {   // *= 0.125 (exact)
    __half2 s = __float2half2_rn(0.125f);
    __half2 r = __hmul2(*reinterpret_cast<__half2*>(&a), s);
    return *reinterpret_cast<uint32_t*>(&r);
}
#define HI_PAIR(v0, v1) __byte_perm((v0), (v1), 0x5410)
#define LO_PAIR(v0, v1) __byte_perm((v0), (v1), 0x7632)

// D(16x8,f32) += A(16x16,f16) * B(16x8,f16)
__device__ __forceinline__ void mma16(float* c, const uint32_t* a, const uint32_t* b) {
    asm volatile(
        "mma.sync.aligned.m16n8k16.row.col.f32.f16.f16.f32 "
        "{%0,%1,%2,%3},{%4,%5,%6,%7},{%8,%9},{%0,%1,%2,%3};"
        : "+f"(c[0]), "+f"(c[1]), "+f"(c[2]), "+f"(c[3])
        : "r"(a[0]), "r"(a[1]), "r"(a[2]), "r"(a[3]), "r"(b[0]), "r"(b[1]));
}
__device__ __forceinline__ void mma3(float* c, const uint32_t* ah, const uint32_t* al,
                                     const uint32_t* bh, const uint32_t* bl) {
    mma16(c, ah, bl);
    mma16(c, al, bh);
    mma16(c, ah, bh);
}

__device__ __forceinline__ void cpa16(uint32_t dst, const void* src) {
    asm volatile("cp.async.cg.shared.global [%0], [%1], 16;" :: "r"(dst), "l"(src));
}

// ===========================================================================
// QKV projection, fused + pipelined (reg-staged double buffer, 1 bar/iter).
// grid (8 heads, 256): bm<224 -> K+V tiles (both weights), bm>=224 -> Q tiles.
// 512 threads, 16 warps (4M x 4N), warp tile 32x16, block tile 128x64, K=32.
// ===========================================================================
#define QKV_AS_U32 (2 * 128 * 40)            // 10240
#define QKV_BS_U32 (2 * 2 * 32 * 68)         // 8704
#define QKV_SMEM   ((QKV_AS_U32 + QKV_BS_U32) * 4)   // 75776 B

__global__ __launch_bounds__(512)
void qkv_kernel(const float* __restrict__ X, const float* __restrict__ Wq,
                const float* __restrict__ Wk, const float* __restrict__ Wv)
{
    extern __shared__ uint32_t sm[];
    uint32_t* As = sm;                 // [2][128][40]
    uint32_t* Bs = sm + QKV_AS_U32;    // [2][2][32][68]

    const int tid  = threadIdx.x;
    const int lane = tid & 31;
    const int warp = tid >> 5;
    const int wm   = warp >> 2;        // 0..3
    const int wn   = warp & 3;         // 0..3
    const int bn   = blockIdx.x;       // head
    const int bm   = blockIdx.y;       // 0..255
    const bool isQ = bm >= 224;

    int bidx, t0, off;
    const float *W0, *W1;
    if (isQ) {
        int qbm = bm - 224;
        bidx = qbm >> 2; t0 = (qbm & 3) * 128; off = 0;
        W0 = Wq + (size_t)bn * DIM * HD; W1 = W0;
    } else {
        bidx = bm / 28; t0 = (bm % 28) * 128; off = QDIM;
        W0 = Wk + (size_t)bn * DIM * HD;
        W1 = Wv + (size_t)bn * DIM * HD;
    }
    const int nw = isQ ? 1 : 2;
    const float* Aptr = X + ((size_t)bidx * TT + t0 + off) * DIM;

    float4 aR[2], bR[2];

    auto ldg = [&](int k0) {
        #pragma unroll
        for (int j = 0; j < 2; j++) {
            int idx = tid + j * 512;
            aR[j] = *reinterpret_cast<const float4*>(
                        Aptr + (size_t)(idx >> 3) * DIM + k0 + (idx & 7) * 4);
        }
        int r = tid >> 4, c4 = tid & 15;
        bR[0] = *reinterpret_cast<const float4*>(W0 + (size_t)(k0 + r) * HD + c4 * 4);
        if (nw == 2)
            bR[1] = *reinterpret_cast<const float4*>(W1 + (size_t)(k0 + r) * HD + c4 * 4);
    };
    auto sts = [&](int st) {
        #pragma unroll
        for (int j = 0; j < 2; j++) {
            int idx = tid + j * 512;
            uint4 p;
            p.x = packsplit(aR[j].x); p.y = packsplit(aR[j].y);
            p.z = packsplit(aR[j].z); p.w = packsplit(aR[j].w);
            *reinterpret_cast<uint4*>(&As[(size_t)(st * 128 + (idx >> 3)) * 40 + (idx & 7) * 4]) = p;
        }
        int r = tid >> 4, c4 = tid & 15;
        #pragma unroll
        for (int w = 0; w < 2; w++)
            if (w < nw) {
                uint4 p;
                p.x = packsplit(bR[w].x); p.y = packsplit(bR[w].y);
                p.z = packsplit(bR[w].z); p.w = packsplit(bR[w].w);
                *reinterpret_cast<uint4*>(&Bs[(size_t)((st * 2 + w) * 32 + r) * 68 + c4 * 4]) = p;
            }
    };

    float acc[2][2][2][4];
    #pragma unroll
    for (int w = 0; w < 2; w++)
        #pragma unroll
        for (int a = 0; a < 2; a++)
            #pragma unroll
            for (int b = 0; b < 2; b++)
                #pragma unroll
                for (int c = 0; c < 4; c++) acc[w][a][b][c] = 0.f;

    ldg(0);
    sts(0);
    ldg(32);
    __syncthreads();

    for (int k = 0; k < 16; k++) {
        const int cur = k & 1;
        if (k < 15) sts(cur ^ 1);
        if (k < 14) ldg((k + 2) * 32);

        #pragma unroll
        for (int kk = 0; kk < 2; kk++) {
            uint32_t ah[2][4], al[2][4];
            #pragma unroll
            for (int mt = 0; mt < 2; mt++) {
                int r0 = wm * 32 + mt * 16 + (lane >> 2);
                int c0 = kk * 16 + 2 * (lane & 3);
                const uint32_t* ap = &As[(size_t)(cur * 128 + r0) * 40 + c0];
                uint2 w01 = *reinterpret_cast<const uint2*>(ap);
                uint2 w23 = *reinterpret_cast<const uint2*>(ap + 8 * 40);
                uint2 w45 = *reinterpret_cast<const uint2*>(ap + 8);
                uint2 w67 = *reinterpret_cast<const uint2*>(ap + 8 * 40 + 8);
                ah[mt][0] = HI_PAIR(w01.x, w01.y); al[mt][0] = LO_PAIR(w01.x, w01.y);
                ah[mt][1] = HI_PAIR(w23.x, w23.y); al[mt][1] = LO_PAIR(w23.x, w23.y);
                ah[mt][2] = HI_PAIR(w45.x, w45.y); al[mt][2] = LO_PAIR(w45.x, w45.y);
                ah[mt][3] = HI_PAIR(w67.x, w67.y); al[mt][3] = LO_PAIR(w67.x, w67.y);
            }
            #pragma unroll
            for (int nt = 0; nt < 2; nt++) {
                int n = wn * 16 + nt * 8 + (lane >> 2);
                int r = kk * 16 + 2 * (lane & 3);
                #pragma unroll
                for (int w = 0; w < 2; w++)
                    if (w < nw) {
                        const uint32_t* bp = &Bs[(size_t)((cur * 2 + w) * 32 + r) * 68 + n];
                        uint32_t v0 = bp[0],      v1 = bp[68];
                        uint32_t v2 = bp[8 * 68], v3 = bp[9 * 68];
                        uint32_t bh[2], bl[2];
                        bh[0] = HI_PAIR(v0, v1); bl[0] = LO_PAIR(v0, v1);
                        bh[1] = HI_PAIR(v2, v3); bl[1] = LO_PAIR(v2, v3);
                        #pragma unroll
                        for (int mt = 0; mt < 2; mt++)
                            mma3(acc[w][mt][nt], ah[mt], al[mt], bh, bl);
                    }
            }
        }
        __syncthreads();
    }

    #pragma unroll
    for (int w = 0; w < 2; w++)
        if (w < nw)
            #pragma unroll
            for (int mt = 0; mt < 2; mt++)
                #pragma unroll
                for (int nt = 0; nt < 2; nt++)
                    #pragma unroll
                    for (int i = 0; i < 4; i++) {
                        int mloc = wm * 32 + mt * 16 + (lane >> 2) + ((i & 2) ? 8 : 0);
                        int nloc = wn * 16 + nt * 8 + 2 * (lane & 3) + (i & 1);
                        uint32_t pv = packsplit(acc[w][mt][nt][i]);
                        if (isQ) {
                            g_Q[(((size_t)(bn * BATCH + bidx)) * QDIM + t0 + mloc) * HD + nloc] = pv;
                        } else {
                            size_t o = (((size_t)(bn * BATCH + bidx)) * GG + t0 + mloc) * HD + nloc;
                            if (w == 0) g_K[o] = pv; else g_V[o] = pv;
                        }
                    }
}

// ===========================================================================
// Out projection, pipelined. A = g_Hd (already packed), B = W_out (split).
// 256 threads, 8 warps (4M x 2N), warp tile 32x32, block tile 128x64, K=32.
// ===========================================================================
#define OP_AS_U32 (2 * 128 * 40)            // 10240
#define OP_BS_U32 (2 * 32 * 68)             // 4352
#define OP_SMEM   ((OP_AS_U32 + OP_BS_U32) * 4)   // 58368 B

__global__ __launch_bounds__(256)
void oproj_kernel(const float* __restrict__ Wo, float* __restrict__ Outp)
{
    extern __shared__ uint32_t sm[];
    uint32_t* As = sm;               // [2][128][40]
    uint32_t* Bs = sm + OP_AS_U32;   // [2][32][68]

    const int tid  = threadIdx.x;
    const int lane = tid & 31;
    const int warp = tid >> 5;
    const int wm   = warp >> 1;      // 0..3
    const int wn   = warp & 1;       // 0..1
    const int bm   = blockIdx.y;     // 0..31
    const int bn   = blockIdx.x;     // 0..7

    const uint32_t* Aptr = g_Hd + (size_t)bm * 128 * 512;
    const float* Wb = Wo + bn * 64;

    uint4  aR[4];
    float4 bR[2];

    auto ldg = [&](int k0) {
        #pragma unroll
        for (int j = 0; j < 4; j++) {
            int idx = tid + j * 256;
            aR[j] = *reinterpret_cast<const uint4*>(
                        Aptr + (size_t)(idx >> 3) * 512 + k0 + (idx & 7) * 4);
        }
        #pragma unroll
        for (int j = 0; j < 2; j++) {
            int idx = tid + j * 256;
            bR[j] = *reinterpret_cast<const float4*>(
                        Wb + (size_t)(k0 + (idx >> 4)) * 512 + (idx & 15) * 4);
        }
    };
    auto sts = [&](int st) {
        #pragma unroll
        for (int j = 0; j < 4; j++) {
            int idx = tid + j * 256;
            *reinterpret_cast<uint4*>(&As[(size_t)(st * 128 + (idx >> 3)) * 40 + (idx & 7) * 4]) = aR[j];
        }
        #pragma unroll
        for (int j = 0; j < 2; j++) {
            int idx = tid + j * 256;
            uint4 p;
            p.x = packsplit(bR[j].x); p.y = packsplit(bR[j].y);
            p.z = packsplit(bR[j].z); p.w = packsplit(bR[j].w);
            *reinterpret_cast<uint4*>(&Bs[(size_t)(st * 32 + (idx >> 4)) * 68 + (idx & 15) * 4]) = p;
        }
    };

    float acc[2][4][4];
    #pragma unroll
    for (int a = 0; a < 2; a++)
        #pragma unroll
        for (int b = 0; b < 4; b++)
            #pragma unroll
            for (int c = 0; c < 4; c++) acc[a][b][c] = 0.f;

    ldg(0);
    sts(0);
    ldg(32);
    __syncthreads();

    for (int k = 0; k < 16; k++) {
        const int cur = k & 1;
        if (k < 15) sts(cur ^ 1);
        if (k < 14) ldg((k + 2) * 32);

        #pragma unroll
        for (int kk = 0; kk < 2; kk++) {
            uint32_t ah[2][4], al[2][4];
            #pragma unroll
            for (int mt = 0; mt < 2; mt++) {
                int r0 = wm * 32 + mt * 16 + (lane >> 2);
                int c0 = kk * 16 + 2 * (lane & 3);
                const uint32_t* ap = &As[(size_t)(cur * 128 + r0) * 40 + c0];
                uint2 w01 = *reinterpret_cast<const uint2*>(ap);
                uint2 w23 = *reinterpret_cast<const uint2*>(ap + 8 * 40);
                uint2 w45 = *reinterpret_cast<const uint2*>(ap + 8);
                uint2 w67 = *reinterpret_cast<const uint2*>(ap + 8 * 40 + 8);
                ah[mt][0] = HI_PAIR(w01.x, w01.y); al[mt][0] = LO_PAIR(w01.x, w01.y);
                ah[mt][1] = HI_PAIR(w23.x, w23.y); al[mt][1] = LO_PAIR(w23.x, w23.y);
                ah[mt][2] = HI_PAIR(w45.x, w45.y); al[mt][2] = LO_PAIR(w45.x, w45.y);
                ah[mt][3] = HI_PAIR(w67.x, w67.y); al[mt][3] = LO_PAIR(w67.x, w67.y);
            }
            #pragma unroll
            for (int nt = 0; nt < 4; nt++) {
                int n = wn * 32 + nt * 8 + (lane >> 2);
                int r = kk * 16 + 2 * (lane & 3);
                const uint32_t* bp = &Bs[(size_t)(cur * 32 + r) * 68 + n];
                uint32_t v0 = bp[0],      v1 = bp[68];
                uint32_t v2 = bp[8 * 68], v3 = bp[9 * 68];
                uint32_t bh[2], bl[2];
                bh[0] = HI_PAIR(v0, v1); bl[0] = LO_PAIR(v0, v1);
                bh[1] = HI_PAIR(v2, v3); bl[1] = LO_PAIR(v2, v3);
                #pragma unroll
                for (int mt = 0; mt < 2; mt++)
                    mma3(acc[mt][nt], ah[mt], al[mt], bh, bl);
            }
        }
        __syncthreads();
    }

    #pragma unroll
    for (int mt = 0; mt < 2; mt++)
        #pragma unroll
        for (int nt = 0; nt < 4; nt++)
            #pragma unroll
            for (int i = 0; i < 4; i++) {
                int mloc = wm * 32 + mt * 16 + (lane >> 2) + ((i & 2) ? 8 : 0);
                int nloc = wn * 32 + nt * 8 + 2 * (lane & 3) + (i & 1);
                Outp[(size_t)(bm * 128 + mloc) * 512 + bn * 64 + nloc] = acc[mt][nt][i];
            }
}

// ===========================================================================
// Flash attention (fp16 2-term): block = (128 q-rows) x (head,batch pair)
// 64-row KV chunks, 3-stage cp.async pipeline, 1 barrier per iteration.
// NORM folded into Q fragments (exact power-of-2 scale).
// ===========================================================================
#define KLD 72
#define VLD 68
#define KS_U32 (64 * KLD)
#define VS_U32 (64 * VLD)
#define STAGE_U32 (KS_U32 + VS_U32)
#define STAGE_BYTES (STAGE_U32 * 4)
#define ATTN_SMEM (3 * STAGE_BYTES)

__device__ __forceinline__ void prefetch_chunk(uint32_t sb, int st,
                                               const uint32_t* Kp, const uint32_t* Vp,
                                               int c, int tid)
{
    uint32_t kb = sb + st * STAGE_BYTES;
    uint32_t vb = kb + KS_U32 * 4;
    const uint32_t* kg = Kp + (size_t)c * 64 * 64;
    const uint32_t* vg = Vp + (size_t)c * 64 * 64;
    #pragma unroll
    for (int j = 0; j < 4; j++) {
        int idx = tid + j * 256;
        int row = idx >> 4, seg = idx & 15;
        cpa16(kb + row * (KLD * 4) + seg * 16, kg + row * 64 + seg * 4);
        cpa16(vb + row * (VLD * 4) + seg * 16, vg + row * 64 + seg * 4);
    }
}

__global__ __launch_bounds__(256)
void attn_kernel()
{
    extern __shared__ uint32_t dsm[];
    const uint32_t sb = (uint32_t)__cvta_generic_to_shared(dsm);

    const int tid  = threadIdx.x;
    const int lane = tid & 31;
    const int warp = tid >> 5;
    const int qt   = blockIdx.x;
    const int pair = blockIdx.y;

    const uint32_t* Qp = g_Q + ((size_t)pair * QDIM + qt * 128 + warp * 16) * HD;
    const uint32_t* Kp = g_K + (size_t)pair * GG * HD;
    const uint32_t* Vp = g_V + (size_t)pair * GG * HD;

    const int r0 = lane >> 2;
    const int j2 = 2 * (lane & 3);

    // Q fragments (hi/lo), NORM pre-folded (exact *0.125)
    uint32_t qh[4][4], ql[4][4];
    #pragma unroll
    for (int kk = 0; kk < 4; kk++) {
        int d0 = kk * 16 + j2;
        uint2 w01 = *reinterpret_cast<const uint2*>(Qp + (size_t)r0 * HD + d0);
        uint2 w23 = *reinterpret_cast<const uint2*>(Qp + (size_t)(r0 + 8) * HD + d0);
        uint2 w45 = *reinterpret_cast<const uint2*>(Qp + (size_t)r0 * HD + d0 + 8);
        uint2 w67 = *reinterpret_cast<const uint2*>(Qp + (size_t)(r0 + 8) * HD + d0 + 8);
        qh[kk][0] = h2scale8(HI_PAIR(w01.x, w01.y)); ql[kk][0] = h2scale8(LO_PAIR(w01.x, w01.y));
        qh[kk][1] = h2scale8(HI_PAIR(w23.x, w23.y)); ql[kk][1] = h2scale8(LO_PAIR(w23.x, w23.y));
        qh[kk][2] = h2scale8(HI_PAIR(w45.x, w45.y)); ql[kk][2] = h2scale8(LO_PAIR(w45.x, w45.y));
        qh[kk][3] = h2scale8(HI_PAIR(w67.x, w67.y)); ql[kk][3] = h2scale8(LO_PAIR(w67.x, w67.y));
    }

    float oacc[8][4];
    #pragma unroll
    for (int t = 0; t < 8; t++)
        #pragma unroll
        for (int i = 0; i < 4; i++) oacc[t][i] = 0.f;
    float m0 = -1e30f, m1 = -1e30f, l0 = 0.f, l1 = 0.f;

    prefetch_chunk(sb, 0, Kp, Vp, 0, tid);
    asm volatile("cp.async.commit_group;");
    prefetch_chunk(sb, 1, Kp, Vp, 1, tid);
    asm volatile("cp.async.commit_group;");

    for (int c = 0; c < NCHUNK; c++) {
        asm volatile("cp.async.wait_group 1;");
        __syncthreads();
        if (c + 2 < NCHUNK)
            prefetch_chunk(sb, (c + 2) % 3, Kp, Vp, c + 2, tid);
        asm volatile("cp.async.commit_group;");

        const uint32_t* Ks = dsm + (c % 3) * STAGE_U32;
        const uint32_t* Vs = Ks + KS_U32;

        float sacc[8][4];
        #pragma unroll
        for (int t = 0; t < 8; t++)
            #pragma unroll
            for (int i = 0; i < 4; i++) sacc[t][i] = 0.f;

        #pragma unroll
        for (int kk = 0; kk < 4; kk++) {
            #pragma unroll
            for (int nt = 0; nt < 8; nt++) {
                int gcol = nt * 8 + r0;
                const uint32_t* p = Ks + gcol * KLD + kk * 16 + j2;
                uint2 w01 = *reinterpret_cast<const uint2*>(p);
                uint2 w23 = *reinterpret_cast<const uint2*>(p + 8);
                uint32_t bh[2], bl[2];
                bh[0] = HI_PAIR(w01.x, w01.y); bl[0] = LO_PAIR(w01.x, w01.y);
                bh[1] = HI_PAIR(w23.x, w23.y); bl[1] = LO_PAIR(w23.x, w23.y);
                mma3(sacc[nt], qh[kk], ql[kk], bh, bl);
            }
        }

        float mx0 = -1e30f, mx1 = -1e30f;
        #pragma unroll
        for (int t = 0; t < 8; t++) {
            mx0 = fmaxf(mx0, fmaxf(sacc[t][0], sacc[t][1]));
            mx1 = fmaxf(mx1, fmaxf(sacc[t][2], sacc[t][3]));
        }
        mx0 = fmaxf(mx0, __shfl_xor_sync(0xffffffffu, mx0, 1));
        mx0 = fmaxf(mx0, __shfl_xor_sync(0xffffffffu, mx0, 2));
        mx1 = fmaxf(mx1, __shfl_xor_sync(0xffffffffu, mx1, 1));
        mx1 = fmaxf(mx1, __shfl_xor_sync(0xffffffffu, mx1, 2));

        float mn0 = fmaxf(m0, mx0), mn1 = fmaxf(m1, mx1);
        float al0 = __expf(m0 - mn0), al1 = __expf(m1 - mn1);
        float s0 = 0.f, s1 = 0.f;
        #pragma unroll
        for (int t = 0; t < 8; t++) {
            sacc[t][0] = __expf(sacc[t][0] - mn0);
            sacc[t][1] = __expf(sacc[t][1] - mn0);
            sacc[t][2] = __expf(sacc[t][2] - mn1);
            sacc[t][3] = __expf(sacc[t][3] - mn1);
            s0 += sacc[t][0] + sacc[t][1];
            s1 += sacc[t][2] + sacc[t][3];
        }
        s0 += __shfl_xor_sync(0xffffffffu, s0, 1);
        s0 += __shfl_xor_sync(0xffffffffu, s0, 2);
        s1 += __shfl_xor_sync(0xffffffffu, s1, 1);
        s1 += __shfl_xor_sync(0xffffffffu, s1, 2);
        l0 = l0 * al0 + s0;
        l1 = l1 * al1 + s1;
        m0 = mn0; m1 = mn1;
        #pragma unroll
        for (int nt = 0; nt < 8; nt++) {
            oacc[nt][0] *= al0; oacc[nt][1] *= al0;
            oacc[nt][2] *= al1; oacc[nt][3] *= al1;
        }

        #pragma unroll
        for (int kk = 0; kk < 4; kk++) {
            uint32_t pah[4], pal[4];
            psplit2(sacc[2 * kk][0],     sacc[2 * kk][1],     pah[0], pal[0]);
            psplit2(sacc[2 * kk][2],     sacc[2 * kk][3],     pah[1], pal[1]);
            psplit2(sacc[2 * kk + 1][0], sacc[2 * kk + 1][1], pah[2], pal[2]);
            psplit2(sacc[2 * kk + 1][2], sacc[2 * kk + 1][3], pah[3], pal[3]);
            int gbase = kk * 16 + j2;
            #pragma unroll
            for (int nt = 0; nt < 8; nt++) {
                int dcol = nt * 8 + r0;
                uint32_t v0 = Vs[gbase * VLD + dcol];
                uint32_t v1 = Vs[(gbase + 1) * VLD + dcol];
                uint32_t v2 = Vs[(gbase + 8) * VLD + dcol];
                uint32_t v3 = Vs[(gbase + 9) * VLD + dcol];
                uint32_t bh[2], bl[2];
                bh[0] = HI_PAIR(v0, v1); bl[0] = LO_PAIR(v0, v1);
                bh[1] = HI_PAIR(v2, v3); bl[1] = LO_PAIR(v2, v3);
                mma3(oacc[nt], pah, pal, bh, bl);
            }
        }
    }

    float inv0 = 1.f / l0, inv1 = 1.f / l1;
    int h = pair >> 3, b = pair & 7;
    #pragma unroll
    for (int nt = 0; nt < 8; nt++)
        #pragma unroll
        for (int i = 0; i < 4; i++) {
            int q = qt * 128 + warp * 16 + r0 + ((i & 2) ? 8 : 0);
            int d = nt * 8 + j2 + (i & 1);
            float v = oacc[nt][i] * ((i & 2) ? inv1 : inv0);
            g_Hd[((size_t)(b * QDIM + q)) * 512 + h * HD + d] = packsplit(v);
        }
}

extern "C" void kernel_launch(void* const* d_in, const int* in_sizes, int n_in,
                              void* d_out, int out_size)
{
    (void)in_sizes; (void)n_in; (void)out_size;
    const float* q  = (const float*)d_in[0];
    const float* Wq = (const float*)d_in[1];
    const float* Wk = (const float*)d_in[2];
    const float* Wv = (const float*)d_in[3];
    const float* Wo = (const float*)d_in[4];
    float* out = (float*)d_out;

    static bool attrs_set = false;
    if (!attrs_set) {
        cudaFuncSetAttribute(qkv_kernel,  cudaFuncAttributeMaxDynamicSharedMemorySize, QKV_SMEM);
        cudaFuncSetAttribute(attn_kernel, cudaFuncAttributeMaxDynamicSharedMemorySize, ATTN_SMEM);
        cudaFuncSetAttribute(oproj_kernel, cudaFuncAttributeMaxDynamicSharedMemorySize, OP_SMEM);
        attrs_set = true;
    }

    qkv_kernel<<<dim3(8, 256), 512, QKV_SMEM>>>(q, Wq, Wk, Wv);
    attn_kernel<<<dim3(4, 64), 256, ATTN_SMEM>>>();
    oproj_kernel<<<dim3(8, 32), 256, OP_SMEM>>>(Wo, out);
}

// round 6
// speedup vs baseline: 1.1985x; 1.1985x over previous
#include <cuda_runtime.h>
#include <cuda_fp16.h>
#include <cstdint>

#define BATCH 8
#define TT    4096
#define DIM   512
#define NH    8
#define HD    64
#define QDIM  512
#define GG    3584
#define NCHUNK 56

// ---- global scratch (u32 = half2 of adjacent elements of ONE plane) ----
__device__ __align__(256) uint32_t g_Q  [(size_t)NH*BATCH*QDIM*HD];        // packed (hi|lo) per element
__device__ __align__(256) uint32_t g_Kh [(size_t)NH*BATCH*GG*(HD/2)];      // [pair][g][dpair]
__device__ __align__(256) uint32_t g_Kl [(size_t)NH*BATCH*GG*(HD/2)];
__device__ __align__(256) uint32_t g_V2h[(size_t)NH*BATCH*(GG/2)*HD];      // [pair][gpair][d]
__device__ __align__(256) uint32_t g_V2l[(size_t)NH*BATCH*(GG/2)*HD];
__device__ __align__(256) uint32_t g_Hdh[(size_t)BATCH*QDIM*(DIM/2)];      // [b][q][epair]
__device__ __align__(256) uint32_t g_Hdl[(size_t)BATCH*QDIM*(DIM/2)];
__device__ __align__(256) uint32_t g_Xh [(size_t)BATCH*TT*(DIM/2)];        // [b][t][kpair]
__device__ __align__(256) uint32_t g_Xl [(size_t)BATCH*TT*(DIM/2)];
__device__ __align__(256) uint32_t g_Wth[(size_t)3*NH*HD*(DIM/2)];         // [w][h][n][kpair]
__device__ __align__(256) uint32_t g_Wtl[(size_t)3*NH*HD*(DIM/2)];
__device__ __align__(256) uint32_t g_Woth[(size_t)DIM*(DIM/2)];            // [n][kpair]
__device__ __align__(256) uint32_t g_Wotl[(size_t)DIM*(DIM/2)];

__device__ __forceinline__ uint32_t packsplit(float v) {
    __half h = __float2half_rn(v);
    __half l = __float2half_rn(v - __half2float(h));
    return (uint32_t)__half_as_ushort(h) | ((uint32_t)__half_as_ushort(l) << 16);
}
__device__ __forceinline__ void psplit2(float p0, float p1, uint32_t& hi, uint32_t& lo) {
    __half2 h = __floats2half2_rn(p0, p1);
    float2 hf = __half22float2(h);
    __half2 l = __floats2half2_rn(p0 - hf.x, p1 - hf.y);
    hi = *reinterpret_cast<uint32_t*>(&h);
    lo = *reinterpret_cast<uint32_t*>(&l);
}
__device__ __forceinline__ uint32_t h2scale8(uint32_t a) {   // *=0.125 exact
    __half2 s = __float2half2_rn(0.125f);
    __half2 r = __hmul2(*reinterpret_cast<__half2*>(&a), s);
    return *reinterpret_cast<uint32_t*>(&r);
}
#define HI_PAIR(v0, v1) __byte_perm((v0), (v1), 0x5410)
#define LO_PAIR(v0, v1) __byte_perm((v0), (v1), 0x7632)

__device__ __forceinline__ void mma16(float* c, const uint32_t* a, const uint32_t* b) {
    asm volatile(
        "mma.sync.aligned.m16n8k16.row.col.f32.f16.f16.f32 "
        "{%0,%1,%2,%3},{%4,%5,%6,%7},{%8,%9},{%0,%1,%2,%3};"
        : "+f"(c[0]), "+f"(c[1]), "+f"(c[2]), "+f"(c[3])
        : "r"(a[0]), "r"(a[1]), "r"(a[2]), "r"(a[3]), "r"(b[0]), "r"(b[1]));
}
__device__ __forceinline__ void mma3(float* c, const uint32_t* ah, const uint32_t* al,
                                     const uint32_t* bh, const uint32_t* bl) {
    mma16(c, ah, bl);
    mma16(c, al, bh);
    mma16(c, ah, bh);
}
__device__ __forceinline__ void cpa16(uint32_t dst, const void* src) {
    asm volatile("cp.async.cg.shared.global [%0], [%1], 16;" :: "r"(dst), "l"(src));
}

// ===========================================================================
// Prep kernels: split inputs into hi/lo half planes (transposed weights)
// ===========================================================================
__global__ __launch_bounds__(256) void splitx_kernel(const float* __restrict__ X) {
    int i = blockIdx.x * 256 + threadIdx.x;              // per float4
    float4 v = reinterpret_cast<const float4*>(X)[i];
    uint32_t h0, l0, h1, l1;
    psplit2(v.x, v.y, h0, l0);
    psplit2(v.z, v.w, h1, l1);
    g_Xh[2 * i] = h0; g_Xh[2 * i + 1] = h1;
    g_Xl[2 * i] = l0; g_Xl[2 * i + 1] = l1;
}
__global__ __launch_bounds__(256) void splitw_qkv_kernel(const float* __restrict__ Wq,
                                                         const float* __restrict__ Wk,
                                                         const float* __restrict__ Wv) {
    int idx = blockIdx.x * 256 + threadIdx.x;   // [w][h][n][kpair] flattened
    int kp = idx & 255, n = (idx >> 8) & 63, h = (idx >> 14) & 7, w = idx >> 17;
    const float* W = (w == 0) ? Wq : (w == 1) ? Wk : Wv;
    const float* b = W + ((size_t)h * DIM + 2 * kp) * HD + n;
    uint32_t hi, lo;
    psplit2(b[0], b[HD], hi, lo);
    g_Wth[idx] = hi; g_Wtl[idx] = lo;
}
__global__ __launch_bounds__(256) void splitw_o_kernel(const float* __restrict__ Wo) {
    int idx = blockIdx.x * 256 + threadIdx.x;   // [n][kpair]
    int kp = idx & 255, n = idx >> 8;
    const float* b = Wo + (size_t)(2 * kp) * DIM + n;
    uint32_t hi, lo;
    psplit2(b[0], b[DIM], hi, lo);
    g_Woth[idx] = hi; g_Wotl[idx] = lo;
}

// ===========================================================================
// QKV projection: plane smem, cp.async 3-buffer pipeline, 1 bar/iter.
// grid (8 heads, 256): bm<224 -> K+V tiles, bm>=224 -> Q tiles.
// 512 thr, 16 warps (4M x 4N), warp 32x16, block 128x64(per weight), K=32.
// ===========================================================================
#define QAS_LD 28
#define QKV_A_U32 (128 * QAS_LD)                      // 3584 per plane
#define QKV_B_U32 (64 * QAS_LD)                       // 1792 per plane per weight
#define QKV_STAGE_U32 (2 * QKV_A_U32 + 4 * QKV_B_U32) // 14336
#define QKV_SMEM (3 * QKV_STAGE_U32 * 4)              // 172032

__global__ __launch_bounds__(512)
void qkv_kernel()
{
    extern __shared__ uint32_t dsm[];
    const uint32_t sb = (uint32_t)__cvta_generic_to_shared(dsm);

    const int tid  = threadIdx.x;
    const int lane = tid & 31;
    const int warp = tid >> 5;
    const int wm   = warp >> 2;
    const int wn   = warp & 3;
    const int bn   = blockIdx.x;     // head
    const int bm   = blockIdx.y;     // 0..255
    const bool isQ = bm >= 224;
    const int r0 = lane >> 2;
    const int j2 = 2 * (lane & 3);

    int bidx, t0, rowoff, w0sel, w1sel;
    if (isQ) {
        int qbm = bm - 224;
        bidx = qbm >> 2; t0 = (qbm & 3) * 128; rowoff = 0; w0sel = 0; w1sel = 0;
    } else {
        bidx = bm / 28; t0 = (bm % 28) * 128; rowoff = QDIM; w0sel = 1; w1sel = 2;
    }
    const int nw = isQ ? 1 : 2;

    const uint32_t* Xhp = g_Xh + ((size_t)bidx * TT + rowoff + t0) * (DIM / 2);
    const uint32_t* Xlp = g_Xl + ((size_t)bidx * TT + rowoff + t0) * (DIM / 2);
    const size_t wb0 = ((size_t)(w0sel * NH + bn)) * HD * (DIM / 2);
    const size_t wb1 = ((size_t)(w1sel * NH + bn)) * HD * (DIM / 2);

    auto prefetch = [&](int st, int it) {
        uint32_t base = sb + st * (QKV_STAGE_U32 * 4);
        // A: 128 rows x 4 chunks x 2 planes = 512 idx, one per thread (FIXED)
        {
            int row = tid >> 2, seg = tid & 3;
            cpa16(base + row * (QAS_LD * 4) + seg * 16,
                  Xhp + (size_t)row * (DIM / 2) + it * 16 + seg * 4);
            cpa16(base + QKV_A_U32 * 4 + row * (QAS_LD * 4) + seg * 16,
                  Xlp + (size_t)row * (DIM / 2) + it * 16 + seg * 4);
        }
        #pragma unroll
        for (int j = 0; j < 2; j++) {          // B: 2w x 2planes x 64 rows x 4 chunks
            int idx = tid + j * 512;
            int w = idx >> 9, rem = idx & 511;
            int p = rem >> 8, r2 = rem & 255;
            int row = r2 >> 2, seg = r2 & 3;
            const uint32_t* src = (p ? g_Wtl : g_Wth) + (w ? wb1 : wb0)
                                  + (size_t)row * (DIM / 2) + it * 16 + seg * 4;
            cpa16(base + (2 * QKV_A_U32 + (w * 2 + p) * QKV_B_U32) * 4
                       + row * (QAS_LD * 4) + seg * 16, src);
        }
    };

    float acc[2][2][2][4];
    #pragma unroll
    for (int w = 0; w < 2; w++)
        #pragma unroll
        for (int a = 0; a < 2; a++)
            #pragma unroll
            for (int b = 0; b < 2; b++)
                #pragma unroll
                for (int c = 0; c < 4; c++) acc[w][a][b][c] = 0.f;

    prefetch(0, 0);
    asm volatile("cp.async.commit_group;");
    prefetch(1, 1);
    asm volatile("cp.async.commit_group;");

    for (int it = 0; it < 16; it++) {
        asm volatile("cp.async.wait_group 1;");
        __syncthreads();
        if (it + 2 < 16) prefetch((it + 2) % 3, it + 2);
        asm volatile("cp.async.commit_group;");

        const uint32_t* Ah = dsm + (it % 3) * QKV_STAGE_U32;
        const uint32_t* Al = Ah + QKV_A_U32;
        const uint32_t* Bb = Ah + 2 * QKV_A_U32;

        #pragma unroll
        for (int kk = 0; kk < 2; kk++) {
            uint32_t ah[2][4], al[2][4];
            #pragma unroll
            for (int mt = 0; mt < 2; mt++) {
                int base = (wm * 32 + mt * 16 + r0) * QAS_LD + kk * 8 + (lane & 3);
                ah[mt][0] = Ah[base];                  al[mt][0] = Al[base];
                ah[mt][1] = Ah[base + 8 * QAS_LD];     al[mt][1] = Al[base + 8 * QAS_LD];
                ah[mt][2] = Ah[base + 4];              al[mt][2] = Al[base + 4];
                ah[mt][3] = Ah[base + 8 * QAS_LD + 4]; al[mt][3] = Al[base + 8 * QAS_LD + 4];
            }
            #pragma unroll
            for (int nt = 0; nt < 2; nt++) {
                int cidx = (wn * 16 + nt * 8 + r0) * QAS_LD + kk * 8 + (lane & 3);
                #pragma unroll
                for (int w = 0; w < 2; w++)
                    if (w < nw) {
                        const uint32_t* Bh = Bb + (w * 2 + 0) * QKV_B_U32;
                        const uint32_t* Bl = Bb + (w * 2 + 1) * QKV_B_U32;
                        uint32_t bh[2], bl[2];
                        bh[0] = Bh[cidx]; bh[1] = Bh[cidx + 4];
                        bl[0] = Bl[cidx]; bl[1] = Bl[cidx + 4];
                        #pragma unroll
                        for (int mt = 0; mt < 2; mt++)
                            mma3(acc[w][mt][nt], ah[mt], al[mt], bh, bl);
                    }
            }
        }
        __syncthreads();
    }

    // Epilogues
    if (isQ) {
        #pragma unroll
        for (int mt = 0; mt < 2; mt++)
            #pragma unroll
            for (int nt = 0; nt < 2; nt++)
                #pragma unroll
                for (int i = 0; i < 4; i++) {
                    int mloc = wm * 32 + mt * 16 + r0 + ((i & 2) ? 8 : 0);
                    int nloc = wn * 16 + nt * 8 + j2 + (i & 1);
                    g_Q[(((size_t)(bn * BATCH + bidx)) * QDIM + t0 + mloc) * HD + nloc] =
                        packsplit(acc[0][mt][nt][i]);
                }
    } else {
        const size_t pb = (size_t)(bn * BATCH + bidx);
        #pragma unroll
        for (int mt = 0; mt < 2; mt++)
            #pragma unroll
            for (int nt = 0; nt < 2; nt++) {
                int grow = t0 + wm * 32 + mt * 16 + r0;
                int dp = wn * 8 + nt * 4 + (lane & 3);
                // K: (d,d+1) pairs
                uint32_t h0, l0, h1, l1;
                psplit2(acc[0][mt][nt][0], acc[0][mt][nt][1], h0, l0);
                psplit2(acc[0][mt][nt][2], acc[0][mt][nt][3], h1, l1);
                size_t kb = (pb * GG + grow) * (HD / 2) + dp;
                g_Kh[kb] = h0; g_Kl[kb] = l0;
                g_Kh[kb + 8 * (HD / 2)] = h1; g_Kl[kb + 8 * (HD / 2)] = l1;
                // V: (g,g+1) pairs via shuffle with lane+4
                uint32_t p0 = packsplit(acc[1][mt][nt][0]);
                uint32_t p1 = packsplit(acc[1][mt][nt][1]);
                uint32_t p2 = packsplit(acc[1][mt][nt][2]);
                uint32_t p3 = packsplit(acc[1][mt][nt][3]);
                uint32_t q0 = __shfl_down_sync(0xffffffffu, p0, 4);
                uint32_t q1 = __shfl_down_sync(0xffffffffu, p1, 4);
                uint32_t q2 = __shfl_down_sync(0xffffffffu, p2, 4);
                uint32_t q3 = __shfl_down_sync(0xffffffffu, p3, 4);
                if ((r0 & 1) == 0) {
                    int d0 = wn * 16 + nt * 8 + j2;
                    size_t vb = (pb * (GG / 2) + (grow >> 1)) * HD + d0;
                    g_V2h[vb]     = HI_PAIR(p0, q0); g_V2l[vb]     = LO_PAIR(p0, q0);
                    g_V2h[vb + 1] = HI_PAIR(p1, q1); g_V2l[vb + 1] = LO_PAIR(p1, q1);
                    g_V2h[vb + 4 * HD]     = HI_PAIR(p2, q2); g_V2l[vb + 4 * HD]     = LO_PAIR(p2, q2);
                    g_V2h[vb + 4 * HD + 1] = HI_PAIR(p3, q3); g_V2l[vb + 4 * HD + 1] = LO_PAIR(p3, q3);
                }
            }
    }
}

// ===========================================================================
// Flash attention: plane smem, 3-buffer cp.async, 1 bar/iter, 2 blocks/SM.
// ===========================================================================
#define AK_LD 36
#define AV_LD 72
#define AK_U32 (64 * AK_LD)                      // 2304 per plane
#define AV_U32 (32 * AV_LD)                      // 2304 per plane
#define ATTN_STAGE_U32 (2 * AK_U32 + 2 * AV_U32) // 9216
#define ATTN_SMEM (3 * ATTN_STAGE_U32 * 4)       // 110592

__global__ __launch_bounds__(256, 2)
void attn_kernel()
{
    extern __shared__ uint32_t dsm[];
    const uint32_t sb = (uint32_t)__cvta_generic_to_shared(dsm);

    const int tid  = threadIdx.x;
    const int lane = tid & 31;
    const int warp = tid >> 5;
    const int qt   = blockIdx.x;
    const int pair = blockIdx.y;
    const int r0 = lane >> 2;
    const int j2 = 2 * (lane & 3);

    const uint32_t* Qp  = g_Q + ((size_t)pair * QDIM + qt * 128 + warp * 16) * HD;
    const size_t kbase = (size_t)pair * GG * (HD / 2);
    const size_t vbase = (size_t)pair * (GG / 2) * HD;

    auto prefetch = [&](int st, int c) {
        uint32_t base = sb + st * (ATTN_STAGE_U32 * 4);
        #pragma unroll
        for (int j = 0; j < 2; j++) {          // K planes: 64 rows x 8 chunks
            int idx = tid + j * 256;
            int row = idx >> 3, seg = idx & 7;
            cpa16(base + row * (AK_LD * 4) + seg * 16,
                  g_Kh + kbase + (size_t)(c * 64 + row) * (HD / 2) + seg * 4);
            cpa16(base + AK_U32 * 4 + row * (AK_LD * 4) + seg * 16,
                  g_Kl + kbase + (size_t)(c * 64 + row) * (HD / 2) + seg * 4);
        }
        #pragma unroll
        for (int j = 0; j < 2; j++) {          // V planes: 32 rows x 16 chunks
            int idx = tid + j * 256;
            int row = idx >> 4, seg = idx & 15;
            cpa16(base + 2 * AK_U32 * 4 + row * (AV_LD * 4) + seg * 16,
                  g_V2h + vbase + (size_t)(c * 32 + row) * HD + seg * 4);
            cpa16(base + (2 * AK_U32 + AV_U32) * 4 + row * (AV_LD * 4) + seg * 16,
                  g_V2l + vbase + (size_t)(c * 32 + row) * HD + seg * 4);
        }
    };

    // Q fragments (packed global, unpack once, NORM folded)
    uint32_t qh[4][4], ql[4][4];
    #pragma unroll
    for (int kk = 0; kk < 4; kk++) {
        int d0 = kk * 16 + j2;
        uint2 w01 = *reinterpret_cast<const uint2*>(Qp + (size_t)r0 * HD + d0);
        uint2 w23 = *reinterpret_cast<const uint2*>(Qp + (size_t)(r0 + 8) * HD + d0);
        uint2 w45 = *reinterpret_cast<const uint2*>(Qp + (size_t)r0 * HD + d0 + 8);
        uint2 w67 = *reinterpret_cast<const uint2*>(Qp + (size_t)(r0 + 8) * HD + d0 + 8);
        qh[kk][0] = h2scale8(HI_PAIR(w01.x, w01.y)); ql[kk][0] = h2scale8(LO_PAIR(w01.x, w01.y));
        qh[kk][1] = h2scale8(HI_PAIR(w23.x, w23.y)); ql[kk][1] = h2scale8(LO_PAIR(w23.x, w23.y));
        qh[kk][2] = h2scale8(HI_PAIR(w45.x, w45.y)); ql[kk][2] = h2scale8(LO_PAIR(w45.x, w45.y));
        qh[kk][3] = h2scale8(HI_PAIR(w67.x, w67.y)); ql[kk][3] = h2scale8(LO_PAIR(w67.x, w67.y));
    }

    float oacc[8][4];
    #pragma unroll
    for (int t = 0; t < 8; t++)
        #pragma unroll
        for (int i = 0; i < 4; i++) oacc[t][i] = 0.f;
    float m0 = -1e30f, m1 = -1e30f, l0 = 0.f, l1 = 0.f;

    prefetch(0, 0);
    asm volatile("cp.async.commit_group;");
    prefetch(1, 1);
    asm volatile("cp.async.commit_group;");

    for (int c = 0; c < NCHUNK; c++) {
        asm volatile("cp.async.wait_group 1;");
        __syncthreads();
        if (c + 2 < NCHUNK) prefetch((c + 2) % 3, c + 2);
        asm volatile("cp.async.commit_group;");

        const uint32_t* Kh = dsm + (c % 3) * ATTN_STAGE_U32;
        const uint32_t* Kl = Kh + AK_U32;
        const uint32_t* Vh = Kh + 2 * AK_U32;
        const uint32_t* Vl = Vh + AV_U32;

        float sacc[8][4];
        #pragma unroll
        for (int t = 0; t < 8; t++)
            #pragma unroll
            for (int i = 0; i < 4; i++) sacc[t][i] = 0.f;

        #pragma unroll
        for (int kk = 0; kk < 4; kk++) {
            #pragma unroll
            for (int nt = 0; nt < 8; nt++) {
                int cidx = (nt * 8 + r0) * AK_LD + kk * 8 + (lane & 3);
                uint32_t bh[2], bl[2];
                bh[0] = Kh[cidx]; bh[1] = Kh[cidx + 4];
                bl[0] = Kl[cidx]; bl[1] = Kl[cidx + 4];
                mma3(sacc[nt], qh[kk], ql[kk], bh, bl);
            }
        }

        float mx0 = -1e30f, mx1 = -1e30f;
        #pragma unroll
        for (int t = 0; t < 8; t++) {
            mx0 = fmaxf(mx0, fmaxf(sacc[t][0], sacc[t][1]));
            mx1 = fmaxf(mx1, fmaxf(sacc[t][2], sacc[t][3]));
        }
        mx0 = fmaxf(mx0, __shfl_xor_sync(0xffffffffu, mx0, 1));
        mx0 = fmaxf(mx0, __shfl_xor_sync(0xffffffffu, mx0, 2));
        mx1 = fmaxf(mx1, __shfl_xor_sync(0xffffffffu, mx1, 1));
        mx1 = fmaxf(mx1, __shfl_xor_sync(0xffffffffu, mx1, 2));

        float mn0 = fmaxf(m0, mx0), mn1 = fmaxf(m1, mx1);
        float al0 = __expf(m0 - mn0), al1 = __expf(m1 - mn1);
        float s0 = 0.f, s1 = 0.f;
        #pragma unroll
        for (int t = 0; t < 8; t++) {
            sacc[t][0] = __expf(sacc[t][0] - mn0);
            sacc[t][1] = __expf(sacc[t][1] - mn0);
            sacc[t][2] = __expf(sacc[t][2] - mn1);
            sacc[t][3] = __expf(sacc[t][3] - mn1);
            s0 += sacc[t][0] + sacc[t][1];
            s1 += sacc[t][2] + sacc[t][3];
        }
        s0 += __shfl_xor_sync(0xffffffffu, s0, 1);
        s0 += __shfl_xor_sync(0xffffffffu, s0, 2);
        s1 += __shfl_xor_sync(0xffffffffu, s1, 1);
        s1 += __shfl_xor_sync(0xffffffffu, s1, 2);
        l0 = l0 * al0 + s0;
        l1 = l1 * al1 + s1;
        m0 = mn0; m1 = mn1;
        #pragma unroll
        for (int nt = 0; nt < 8; nt++) {
            oacc[nt][0] *= al0; oacc[nt][1] *= al0;
            oacc[nt][2] *= al1; oacc[nt][3] *= al1;
        }

        #pragma unroll
        for (int kk = 0; kk < 4; kk++) {
            uint32_t pah[4], pal[4];
            psplit2(sacc[2 * kk][0],     sacc[2 * kk][1],     pah[0], pal[0]);
            psplit2(sacc[2 * kk][2],     sacc[2 * kk][3],     pah[1], pal[1]);
            psplit2(sacc[2 * kk + 1][0], sacc[2 * kk + 1][1], pah[2], pal[2]);
            psplit2(sacc[2 * kk + 1][2], sacc[2 * kk + 1][3], pah[3], pal[3]);
            int gp = kk * 8 + (lane & 3);
            #pragma unroll
            for (int nt = 0; nt < 8; nt++) {
                int d = nt * 8 + r0;
                uint32_t bh[2], bl[2];
                bh[0] = Vh[gp * AV_LD + d]; bh[1] = Vh[(gp + 4) * AV_LD + d];
                bl[0] = Vl[gp * AV_LD + d]; bl[1] = Vl[(gp + 4) * AV_LD + d];
                mma3(oacc[nt], pah, pal, bh, bl);
            }
        }
    }

    float inv0 = 1.f / l0, inv1 = 1.f / l1;
    int h = pair >> 3, b = pair & 7;
    #pragma unroll
    for (int nt = 0; nt < 8; nt++) {
        int q = qt * 128 + warp * 16 + r0;
        int dp = h * 32 + nt * 4 + (lane & 3);
        uint32_t h0, l0u, h1, l1u;
        psplit2(oacc[nt][0] * inv0, oacc[nt][1] * inv0, h0, l0u);
        psplit2(oacc[nt][2] * inv1, oacc[nt][3] * inv1, h1, l1u);
        size_t o = ((size_t)(b * QDIM + q)) * (DIM / 2) + dp;
        g_Hdh[o] = h0; g_Hdl[o] = l0u;
        g_Hdh[o + 8 * (DIM / 2)] = h1; g_Hdl[o + 8 * (DIM / 2)] = l1u;
    }
}

// ===========================================================================
// Out projection: plane smem, cp.async 3-buffer, 1 bar/iter.
// 256 thr, 8 warps (4M x 2N), warp 32x32, block 128x64, K=32.
// ===========================================================================
#define OP_A_U32 (128 * QAS_LD)                    // 3584 per plane
#define OP_B_U32 (64 * QAS_LD)                     // 1792 per plane
#define OP_STAGE_U32 (2 * OP_A_U32 + 2 * OP_B_U32) // 10752
#define OP_SMEM (3 * OP_STAGE_U32 * 4)             // 129024

__global__ __launch_bounds__(256)
void oproj_kernel(float* __restrict__ Outp)
{
    extern __shared__ uint32_t dsm[];
    const uint32_t sb = (uint32_t)__cvta_generic_to_shared(dsm);

    const int tid  = threadIdx.x;
    const int lane = tid & 31;
    const int warp = tid >> 5;
    const int wm   = warp >> 1;
    const int wn   = warp & 1;
    const int bm   = blockIdx.y;
    const int bn   = blockIdx.x;
    const int r0 = lane >> 2;
    const int j2 = 2 * (lane & 3);

    const size_t arow = (size_t)bm * 128;
    const size_t brow = (size_t)bn * 64;

    auto prefetch = [&](int st, int it) {
        uint32_t base = sb + st * (OP_STAGE_U32 * 4);
        #pragma unroll
        for (int j = 0; j < 4; j++) {          // A: 2 planes x 128 rows x 4 chunks
            int idx = tid + j * 256;
            int p = idx >> 9, rem = idx & 511;
            int row = rem >> 2, seg = rem & 3;
            cpa16(base + p * (OP_A_U32 * 4) + row * (QAS_LD * 4) + seg * 16,
                  (p ? g_Hdl : g_Hdh) + (arow + row) * (DIM / 2) + it * 16 + seg * 4);
        }
        #pragma unroll
        for (int j = 0; j < 2; j++) {          // B: 2 planes x 64 rows x 4 chunks
            int idx = tid + j * 256;
            int p = idx >> 8, rem = idx & 255;
            int row = rem >> 2, seg = rem & 3;
            cpa16(base + (2 * OP_A_U32 + p * OP_B_U32) * 4 + row * (QAS_LD * 4) + seg * 16,
                  (p ? g_Wotl : g_Woth) + (brow + row) * (DIM / 2) + it * 16 + seg * 4);
        }
    };

    float acc[2][4][4];
    #pragma unroll
    for (int a = 0; a < 2; a++)
        #pragma unroll
        for (int b = 0; b < 4; b++)
            #pragma unroll
            for (int c = 0; c < 4; c++) acc[a][b][c] = 0.f;

    prefetch(0, 0);
    asm volatile("cp.async.commit_group;");
    prefetch(1, 1);
    asm volatile("cp.async.commit_group;");

    for (int it = 0; it < 16; it++) {
        asm volatile("cp.async.wait_group 1;");
        __syncthreads();
        if (it + 2 < 16) prefetch((it + 2) % 3, it + 2);
        asm volatile("cp.async.commit_group;");

        const uint32_t* Ah = dsm + (it % 3) * OP_STAGE_U32;
        const uint32_t* Al = Ah + OP_A_U32;
        const uint32_t* Bh = Ah + 2 * OP_A_U32;
        const uint32_t* Bl = Bh + OP_B_U32;

        #pragma unroll
        for (int kk = 0; kk < 2; kk++) {
            uint32_t ah[2][4], al[2][4];
            #pragma unroll
            for (int mt = 0; mt < 2; mt++) {
                int base = (wm * 32 + mt * 16 + r0) * QAS_LD + kk * 8 + (lane & 3);
                ah[mt][0] = Ah[base];                  al[mt][0] = Al[base];
                ah[mt][1] = Ah[base + 8 * QAS_LD];     al[mt][1] = Al[base + 8 * QAS_LD];
                ah[mt][2] = Ah[base + 4];              al[mt][2] = Al[base + 4];
                ah[mt][3] = Ah[base + 8 * QAS_LD + 4]; al[mt][3] = Al[base + 8 * QAS_LD + 4];
            }
            #pragma unroll
            for (int nt = 0; nt < 4; nt++) {
                int cidx = (wn * 32 + nt * 8 + r0) * QAS_LD + kk * 8 + (lane & 3);
                uint32_t bh[2], bl[2];
                bh[0] = Bh[cidx]; bh[1] = Bh[cidx + 4];
                bl[0] = Bl[cidx]; bl[1] = Bl[cidx + 4];
                #pragma unroll
                for (int mt = 0; mt < 2; mt++)
                    mma3(acc[mt][nt], ah[mt], al[mt], bh, bl);
            }
        }
        __syncthreads();
    }

    #pragma unroll
    for (int mt = 0; mt < 2; mt++)
        #pragma unroll
        for (int nt = 0; nt < 4; nt++)
            #pragma unroll
            for (int i = 0; i < 4; i++) {
                int mloc = wm * 32 + mt * 16 + r0 + ((i & 2) ? 8 : 0);
                int nloc = wn * 32 + nt * 8 + j2 + (i & 1);
                Outp[(size_t)(bm * 128 + mloc) * DIM + bn * 64 + nloc] = acc[mt][nt][i];
            }
}

extern "C" void kernel_launch(void* const* d_in, const int* in_sizes, int n_in,
                              void* d_out, int out_size)
{
    (void)in_sizes; (void)n_in; (void)out_size;
    const float* q  = (const float*)d_in[0];
    const float* Wq = (const float*)d_in[1];
    const float* Wk = (const float*)d_in[2];
    const float* Wv = (const float*)d_in[3];
    const float* Wo = (const float*)d_in[4];
    float* out = (float*)d_out;

    static bool attrs_set = false;
    if (!attrs_set) {
        cudaFuncSetAttribute(qkv_kernel,   cudaFuncAttributeMaxDynamicSharedMemorySize, QKV_SMEM);
        cudaFuncSetAttribute(attn_kernel,  cudaFuncAttributeMaxDynamicSharedMemorySize, ATTN_SMEM);
        cudaFuncSetAttribute(oproj_kernel, cudaFuncAttributeMaxDynamicSharedMemorySize, OP_SMEM);
        attrs_set = true;
    }

    splitx_kernel<<<16384, 256>>>(q);                       // X -> hi/lo planes
    splitw_qkv_kernel<<<1536, 256>>>(Wq, Wk, Wv);           // W^T planes
    splitw_o_kernel<<<512, 256>>>(Wo);
    qkv_kernel<<<dim3(8, 256), 512, QKV_SMEM>>>();
    attn_kernel<<<dim3(4, 64), 256, ATTN_SMEM>>>();
    oproj_kernel<<<dim3(8, 32), 256, OP_SMEM>>>(out);
}

// round 8
// speedup vs baseline: 1.2437x; 1.0377x over previous
#include <cuda_runtime.h>
#include <cuda_fp16.h>
#include <cstdint>

#define BATCH 8
#define TT    4096
#define DIM   512
#define NH    8
#define HD    64
#define QDIM  512
#define GG    3584
#define NCHUNK 56

// ---- global scratch (u32 = half2 of adjacent elements of ONE plane) ----
__device__ __align__(256) uint32_t g_Q  [(size_t)NH*BATCH*QDIM*HD];        // packed (hi|lo) per element
__device__ __align__(256) uint32_t g_Kh [(size_t)NH*BATCH*GG*(HD/2)];      // [pair][g][dpair]
__device__ __align__(256) uint32_t g_Kl [(size_t)NH*BATCH*GG*(HD/2)];
__device__ __align__(256) uint32_t g_V2h[(size_t)NH*BATCH*(GG/2)*HD];      // [pair][gpair][d]
__device__ __align__(256) uint32_t g_V2l[(size_t)NH*BATCH*(GG/2)*HD];
__device__ __align__(256) uint32_t g_Hdh[(size_t)BATCH*QDIM*(DIM/2)];      // [b][q][epair]
__device__ __align__(256) uint32_t g_Hdl[(size_t)BATCH*QDIM*(DIM/2)];
__device__ __align__(256) uint32_t g_Xh [(size_t)BATCH*TT*(DIM/2)];        // [b][t][kpair]
__device__ __align__(256) uint32_t g_Xl [(size_t)BATCH*TT*(DIM/2)];
__device__ __align__(256) uint32_t g_Wth[(size_t)3*NH*HD*(DIM/2)];         // [w][h][n][kpair]
__device__ __align__(256) uint32_t g_Wtl[(size_t)3*NH*HD*(DIM/2)];
__device__ __align__(256) uint32_t g_Woth[(size_t)DIM*(DIM/2)];            // [n][kpair]
__device__ __align__(256) uint32_t g_Wotl[(size_t)DIM*(DIM/2)];

__device__ __forceinline__ uint32_t packsplit(float v) {
    __half h = __float2half_rn(v);
    __half l = __float2half_rn(v - __half2float(h));
    return (uint32_t)__half_as_ushort(h) | ((uint32_t)__half_as_ushort(l) << 16);
}
__device__ __forceinline__ void psplit2(float p0, float p1, uint32_t& hi, uint32_t& lo) {
    __half2 h = __floats2half2_rn(p0, p1);
    float2 hf = __half22float2(h);
    __half2 l = __floats2half2_rn(p0 - hf.x, p1 - hf.y);
    hi = *reinterpret_cast<uint32_t*>(&h);
    lo = *reinterpret_cast<uint32_t*>(&l);
}
__device__ __forceinline__ uint32_t h2scale8(uint32_t a) {   // *=0.125 exact
    __half2 s = __float2half2_rn(0.125f);
    __half2 r = __hmul2(*reinterpret_cast<__half2*>(&a), s);
    return *reinterpret_cast<uint32_t*>(&r);
}
#define HI_PAIR(v0, v1) __byte_perm((v0), (v1), 0x5410)
#define LO_PAIR(v0, v1) __byte_perm((v0), (v1), 0x7632)

__device__ __forceinline__ void mma16(float* c, const uint32_t* a, const uint32_t* b) {
    asm volatile(
        "mma.sync.aligned.m16n8k16.row.col.f32.f16.f16.f32 "
        "{%0,%1,%2,%3},{%4,%5,%6,%7},{%8,%9},{%0,%1,%2,%3};"
        : "+f"(c[0]), "+f"(c[1]), "+f"(c[2]), "+f"(c[3])
        : "r"(a[0]), "r"(a[1]), "r"(a[2]), "r"(a[3]), "r"(b[0]), "r"(b[1]));
}
__device__ __forceinline__ void mma3(float* c, const uint32_t* ah, const uint32_t* al,
                                     const uint32_t* bh, const uint32_t* bl) {
    mma16(c, ah, bl);
    mma16(c, al, bh);
    mma16(c, ah, bh);
}
__device__ __forceinline__ void cpa16(uint32_t dst, const void* src) {
    asm volatile("cp.async.cg.shared.global [%0], [%1], 16;" :: "r"(dst), "l"(src));
}

// ===========================================================================
// Prep kernels: split inputs into hi/lo half planes (transposed weights)
// ===========================================================================
__global__ __launch_bounds__(256) void splitx_kernel(const float* __restrict__ X) {
    int i = blockIdx.x * 256 + threadIdx.x;              // per float4
    float4 v = reinterpret_cast<const float4*>(X)[i];
    uint32_t h0, l0, h1, l1;
    psplit2(v.x, v.y, h0, l0);
    psplit2(v.z, v.w, h1, l1);
    g_Xh[2 * i] = h0; g_Xh[2 * i + 1] = h1;
    g_Xl[2 * i] = l0; g_Xl[2 * i + 1] = l1;
}
__global__ __launch_bounds__(256) void splitw_qkv_kernel(const float* __restrict__ Wq,
                                                         const float* __restrict__ Wk,
                                                         const float* __restrict__ Wv) {
    int idx = blockIdx.x * 256 + threadIdx.x;   // [w][h][n][kpair] flattened
    int kp = idx & 255, n = (idx >> 8) & 63, h = (idx >> 14) & 7, w = idx >> 17;
    const float* W = (w == 0) ? Wq : (w == 1) ? Wk : Wv;
    const float* b = W + ((size_t)h * DIM + 2 * kp) * HD + n;
    uint32_t hi, lo;
    psplit2(b[0], b[HD], hi, lo);
    g_Wth[idx] = hi; g_Wtl[idx] = lo;
}
__global__ __launch_bounds__(256) void splitw_o_kernel(const float* __restrict__ Wo) {
    int idx = blockIdx.x * 256 + threadIdx.x;   // [n][kpair]
    int kp = idx & 255, n = idx >> 8;
    const float* b = Wo + (size_t)(2 * kp) * DIM + n;
    uint32_t hi, lo;
    psplit2(b[0], b[DIM], hi, lo);
    g_Woth[idx] = hi; g_Wotl[idx] = lo;
}

// ===========================================================================
// QKV projection: 256 thr, 8 warps (4M x 2N), warp tile 32x32 per weight,
// block tile 128x64(per weight), K-chunk 16 halfs, 3-stage cp.async,
// 1 bar/iter, 2 blocks/SM (72KB smem).
// grid (8 heads, 256): bm<224 -> K+V tiles, bm>=224 -> Q tiles.
// ===========================================================================
#define GLD 12                                     // row stride u32 (8 data + 4 pad)
#define QKV_A_U32 (128 * GLD)                      // 1536 per plane
#define QKV_B_U32 (64 * GLD)                       // 768 per plane per weight
#define QKV_STAGE_U32 (2 * QKV_A_U32 + 4 * QKV_B_U32) // 6144
#define QKV_SMEM (3 * QKV_STAGE_U32 * 4)           // 73728

__global__ __launch_bounds__(256, 2)
void qkv_kernel()
{
    extern __shared__ uint32_t dsm[];
    const uint32_t sb = (uint32_t)__cvta_generic_to_shared(dsm);

    const int tid  = threadIdx.x;
    const int lane = tid & 31;
    const int warp = tid >> 5;
    const int wm   = warp >> 1;      // 0..3
    const int wn   = warp & 1;       // 0..1
    const int bn   = blockIdx.x;     // head
    const int bm   = blockIdx.y;     // 0..255
    const bool isQ = bm >= 224;
    const int r0 = lane >> 2;
    const int j2 = 2 * (lane & 3);

    int bidx, t0, rowoff, w0sel, w1sel;
    if (isQ) {
        int qbm = bm - 224;
        bidx = qbm >> 2; t0 = (qbm & 3) * 128; rowoff = 0; w0sel = 0; w1sel = 0;
    } else {
        bidx = bm / 28; t0 = (bm % 28) * 128; rowoff = QDIM; w0sel = 1; w1sel = 2;
    }
    const int nw = isQ ? 1 : 2;

    const uint32_t* Xhp = g_Xh + ((size_t)bidx * TT + rowoff + t0) * (DIM / 2);
    const uint32_t* Xlp = g_Xl + ((size_t)bidx * TT + rowoff + t0) * (DIM / 2);
    const size_t wb0 = ((size_t)(w0sel * NH + bn)) * HD * (DIM / 2);
    const size_t wb1 = ((size_t)(w1sel * NH + bn)) * HD * (DIM / 2);

    auto prefetch = [&](int st, int c) {
        uint32_t base = sb + st * (QKV_STAGE_U32 * 4);
        #pragma unroll
        for (int j = 0; j < 2; j++) {      // A: 2 planes x 128 rows x 2 segs = 512
            int idx = tid + j * 256;
            int p = idx >> 8, rem = idx & 255;
            int row = rem >> 1, seg = rem & 1;
            cpa16(base + p * (QKV_A_U32 * 4) + row * (GLD * 4) + seg * 16,
                  (p ? Xlp : Xhp) + (size_t)row * (DIM / 2) + c * 8 + seg * 4);
        }
        #pragma unroll
        for (int j = 0; j < 2; j++) {      // B: 2w x 2p x 64 rows x 2 segs = 512
            int idx = tid + j * 256;
            int w = idx >> 8, rem = idx & 255;
            int p = (rem >> 7) & 1, r2 = rem & 127;
            int row = r2 >> 1, seg = r2 & 1;
            if (w < nw) {
                const uint32_t* src = (p ? g_Wtl : g_Wth) + (w ? wb1 : wb0)
                                      + (size_t)row * (DIM / 2) + c * 8 + seg * 4;
                cpa16(base + (2 * QKV_A_U32 + (w * 2 + p) * QKV_B_U32) * 4
                           + row * (GLD * 4) + seg * 16, src);
            }
        }
    };

    float acc[2][2][4][4];     // [w][mt][nt][i]
    #pragma unroll
    for (int w = 0; w < 2; w++)
        #pragma unroll
        for (int a = 0; a < 2; a++)
            #pragma unroll
            for (int b = 0; b < 4; b++)
                #pragma unroll
                for (int c = 0; c < 4; c++) acc[w][a][b][c] = 0.f;

    prefetch(0, 0);
    asm volatile("cp.async.commit_group;");
    prefetch(1, 1);
    asm volatile("cp.async.commit_group;");

    for (int it = 0; it < 32; it++) {
        asm volatile("cp.async.wait_group 1;");
        __syncthreads();
        if (it + 2 < 32) prefetch((it + 2) % 3, it + 2);
        asm volatile("cp.async.commit_group;");

        const uint32_t* Ah = dsm + (it % 3) * QKV_STAGE_U32;
        const uint32_t* Al = Ah + QKV_A_U32;
        const uint32_t* Bb = Ah + 2 * QKV_A_U32;

        uint32_t ah[2][4], al[2][4];
        #pragma unroll
        for (int mt = 0; mt < 2; mt++) {
            int base = (wm * 32 + mt * 16 + r0) * GLD + (lane & 3);
            ah[mt][0] = Ah[base];           al[mt][0] = Al[base];
            ah[mt][1] = Ah[base + 8 * GLD]; al[mt][1] = Al[base + 8 * GLD];
            ah[mt][2] = Ah[base + 4];       al[mt][2] = Al[base + 4];
            ah[mt][3] = Ah[base + 8 * GLD + 4]; al[mt][3] = Al[base + 8 * GLD + 4];
        }
        #pragma unroll
        for (int nt = 0; nt < 4; nt++) {
            int cidx = (wn * 32 + nt * 8 + r0) * GLD + (lane & 3);
            #pragma unroll
            for (int w = 0; w < 2; w++)
                if (w < nw) {
                    const uint32_t* Bh = Bb + (w * 2 + 0) * QKV_B_U32;
                    const uint32_t* Bl = Bb + (w * 2 + 1) * QKV_B_U32;
                    uint32_t bh[2], bl[2];
                    bh[0] = Bh[cidx]; bh[1] = Bh[cidx + 4];
                    bl[0] = Bl[cidx]; bl[1] = Bl[cidx + 4];
                    #pragma unroll
                    for (int mt = 0; mt < 2; mt++)
                        mma3(acc[w][mt][nt], ah[mt], al[mt], bh, bl);
                }
        }
        __syncthreads();
    }

    // Epilogues
    if (isQ) {
        #pragma unroll
        for (int mt = 0; mt < 2; mt++)
            #pragma unroll
            for (int nt = 0; nt < 4; nt++)
                #pragma unroll
                for (int i = 0; i < 4; i++) {
                    int mloc = wm * 32 + mt * 16 + r0 + ((i & 2) ? 8 : 0);
                    int nloc = wn * 32 + nt * 8 + j2 + (i & 1);
                    g_Q[(((size_t)(bn * BATCH + bidx)) * QDIM + t0 + mloc) * HD + nloc] =
                        packsplit(acc[0][mt][nt][i]);
                }
    } else {
        const size_t pb = (size_t)(bn * BATCH + bidx);
        #pragma unroll
        for (int mt = 0; mt < 2; mt++)
            #pragma unroll
            for (int nt = 0; nt < 4; nt++) {
                int grow = t0 + wm * 32 + mt * 16 + r0;
                int dp = wn * 16 + nt * 4 + (lane & 3);
                // K: (d,d+1) pairs
                uint32_t h0, l0, h1, l1;
                psplit2(acc[0][mt][nt][0], acc[0][mt][nt][1], h0, l0);
                psplit2(acc[0][mt][nt][2], acc[0][mt][nt][3], h1, l1);
                size_t kb = (pb * GG + grow) * (HD / 2) + dp;
                g_Kh[kb] = h0; g_Kl[kb] = l0;
                g_Kh[kb + 8 * (HD / 2)] = h1; g_Kl[kb + 8 * (HD / 2)] = l1;
                // V: (g,g+1) pairs via shuffle with lane+4
                uint32_t p0 = packsplit(acc[1][mt][nt][0]);
                uint32_t p1 = packsplit(acc[1][mt][nt][1]);
                uint32_t p2 = packsplit(acc[1][mt][nt][2]);
                uint32_t p3 = packsplit(acc[1][mt][nt][3]);
                uint32_t q0 = __shfl_down_sync(0xffffffffu, p0, 4);
                uint32_t q1 = __shfl_down_sync(0xffffffffu, p1, 4);
                uint32_t q2 = __shfl_down_sync(0xffffffffu, p2, 4);
                uint32_t q3 = __shfl_down_sync(0xffffffffu, p3, 4);
                if ((r0 & 1) == 0) {
                    int d0 = wn * 32 + nt * 8 + j2;
                    size_t vb = (pb * (GG / 2) + (grow >> 1)) * HD + d0;
                    g_V2h[vb]     = HI_PAIR(p0, q0); g_V2l[vb]     = LO_PAIR(p0, q0);
                    g_V2h[vb + 1] = HI_PAIR(p1, q1); g_V2l[vb + 1] = LO_PAIR(p1, q1);
                    g_V2h[vb + 4 * HD]     = HI_PAIR(p2, q2); g_V2l[vb + 4 * HD]     = LO_PAIR(p2, q2);
                    g_V2h[vb + 4 * HD + 1] = HI_PAIR(p3, q3); g_V2l[vb + 4 * HD + 1] = LO_PAIR(p3, q3);
                }
            }
    }
}

// ===========================================================================
// Out projection: 256 thr, 8 warps (4M x 2N), warp 32x32, block 128x64,
// K-chunk 16, 3-stage cp.async, 2 blocks/SM (54KB smem).
// ===========================================================================
#define OP_A_U32 (128 * GLD)                       // 1536 per plane
#define OP_B_U32 (64 * GLD)                        // 768 per plane
#define OP_STAGE_U32 (2 * OP_A_U32 + 2 * OP_B_U32) // 4608
#define OP_SMEM (3 * OP_STAGE_U32 * 4)             // 55296

__global__ __launch_bounds__(256, 2)
void oproj_kernel(float* __restrict__ Outp)
{
    extern __shared__ uint32_t dsm[];
    const uint32_t sb = (uint32_t)__cvta_generic_to_shared(dsm);

    const int tid  = threadIdx.x;
    const int lane = tid & 31;
    const int warp = tid >> 5;
    const int wm   = warp >> 1;
    const int wn   = warp & 1;
    const int bm   = blockIdx.y;
    const int bn   = blockIdx.x;
    const int r0 = lane >> 2;
    const int j2 = 2 * (lane & 3);

    const size_t arow = (size_t)bm * 128;
    const size_t brow = (size_t)bn * 64;

    auto prefetch = [&](int st, int c) {
        uint32_t base = sb + st * (OP_STAGE_U32 * 4);
        #pragma unroll
        for (int j = 0; j < 2; j++) {      // A: 2 planes x 128 rows x 2 segs
            int idx = tid + j * 256;
            int p = idx >> 8, rem = idx & 255;
            int row = rem >> 1, seg = rem & 1;
            cpa16(base + p * (OP_A_U32 * 4) + row * (GLD * 4) + seg * 16,
                  (p ? g_Hdl : g_Hdh) + (arow + row) * (DIM / 2) + c * 8 + seg * 4);
        }
        {                                   // B: 2 planes x 64 rows x 2 segs = 256
            int p = tid >> 7, rem = tid & 127;
            int row = rem >> 1, seg = rem & 1;
            cpa16(base + (2 * OP_A_U32 + p * OP_B_U32) * 4 + row * (GLD * 4) + seg * 16,
                  (p ? g_Wotl : g_Woth) + (brow + row) * (DIM / 2) + c * 8 + seg * 4);
        }
    };

    float acc[2][4][4];
    #pragma unroll
    for (int a = 0; a < 2; a++)
        #pragma unroll
        for (int b = 0; b < 4; b++)
            #pragma unroll
            for (int c = 0; c < 4; c++) acc[a][b][c] = 0.f;

    prefetch(0, 0);
    asm volatile("cp.async.commit_group;");
    prefetch(1, 1);
    asm volatile("cp.async.commit_group;");

    for (int it = 0; it < 32; it++) {
        asm volatile("cp.async.wait_group 1;");
        __syncthreads();
        if (it + 2 < 32) prefetch((it + 2) % 3, it + 2);
        asm volatile("cp.async.commit_group;");

        const uint32_t* Ah = dsm + (it % 3) * OP_STAGE_U32;
        const uint32_t* Al = Ah + OP_A_U32;
        const uint32_t* Bh = Ah + 2 * OP_A_U32;
        const uint32_t* Bl = Bh + OP_B_U32;

        uint32_t ah[2][4], al[2][4];
        #pragma unroll
        for (int mt = 0; mt < 2; mt++) {
            int base = (wm * 32 + mt * 16 + r0) * GLD + (lane & 3);
            ah[mt][0] = Ah[base];           al[mt][0] = Al[base];
            ah[mt][1] = Ah[base + 8 * GLD]; al[mt][1] = Al[base + 8 * GLD];
            ah[mt][2] = Ah[base + 4];       al[mt][2] = Al[base + 4];
            ah[mt][3] = Ah[base + 8 * GLD + 4]; al[mt][3] = Al[base + 8 * GLD + 4];
        }
        #pragma unroll
        for (int nt = 0; nt < 4; nt++) {
            int cidx = (wn * 32 + nt * 8 + r0) * GLD + (lane & 3);
            uint32_t bh[2], bl[2];
            bh[0] = Bh[cidx]; bh[1] = Bh[cidx + 4];
            bl[0] = Bl[cidx]; bl[1] = Bl[cidx + 4];
            #pragma unroll
            for (int mt = 0; mt < 2; mt++)
                mma3(acc[mt][nt], ah[mt], al[mt], bh, bl);
        }
        __syncthreads();
    }

    #pragma unroll
    for (int mt = 0; mt < 2; mt++)
        #pragma unroll
        for (int nt = 0; nt < 4; nt++)
            #pragma unroll
            for (int i = 0; i < 4; i++) {
                int mloc = wm * 32 + mt * 16 + r0 + ((i & 2) ? 8 : 0);
                int nloc = wn * 32 + nt * 8 + j2 + (i & 1);
                Outp[(size_t)(bm * 128 + mloc) * DIM + bn * 64 + nloc] = acc[mt][nt][i];
            }
}

// ===========================================================================
// Flash attention: plane smem, 3-buffer cp.async, 1 bar/iter, 2 blocks/SM.
// (unchanged from round 6 — passing at rel_err 2.1e-5)
// ===========================================================================
#define AK_LD 36
#define AV_LD 72
#define AK_U32 (64 * AK_LD)
#define AV_U32 (32 * AV_LD)
#define ATTN_STAGE_U32 (2 * AK_U32 + 2 * AV_U32)
#define ATTN_SMEM (3 * ATTN_STAGE_U32 * 4)

__global__ __launch_bounds__(256, 2)
void attn_kernel()
{
    extern __shared__ uint32_t dsm[];
    const uint32_t sb = (uint32_t)__cvta_generic_to_shared(dsm);

    const int tid  = threadIdx.x;
    const int lane = tid & 31;
    const int warp = tid >> 5;
    const int qt   = blockIdx.x;
    const int pair = blockIdx.y;
    const int r0 = lane >> 2;
    const int j2 = 2 * (lane & 3);

    const uint32_t* Qp  = g_Q + ((size_t)pair * QDIM + qt * 128 + warp * 16) * HD;
    const size_t kbase = (size_t)pair * GG * (HD / 2);
    const size_t vbase = (size_t)pair * (GG / 2) * HD;

    auto prefetch = [&](int st, int c) {
        uint32_t base = sb + st * (ATTN_STAGE_U32 * 4);
        #pragma unroll
        for (int j = 0; j < 2; j++) {
            int idx = tid + j * 256;
            int row = idx >> 3, seg = idx & 7;
            cpa16(base + row * (AK_LD * 4) + seg * 16,
                  g_Kh + kbase + (size_t)(c * 64 + row) * (HD / 2) + seg * 4);
            cpa16(base + AK_U32 * 4 + row * (AK_LD * 4) + seg * 16,
                  g_Kl + kbase + (size_t)(c * 64 + row) * (HD / 2) + seg * 4);
        }
        #pragma unroll
        for (int j = 0; j < 2; j++) {
            int idx = tid + j * 256;
            int row = idx >> 4, seg = idx & 15;
            cpa16(base + 2 * AK_U32 * 4 + row * (AV_LD * 4) + seg * 16,
                  g_V2h + vbase + (size_t)(c * 32 + row) * HD + seg * 4);
            cpa16(base + (2 * AK_U32 + AV_U32) * 4 + row * (AV_LD * 4) + seg * 16,
                  g_V2l + vbase + (size_t)(c * 32 + row) * HD + seg * 4);
        }
    };

    uint32_t qh[4][4], ql[4][4];
    #pragma unroll
    for (int kk = 0; kk < 4; kk++) {
        int d0 = kk * 16 + j2;
        uint2 w01 = *reinterpret_cast<const uint2*>(Qp + (size_t)r0 * HD + d0);
        uint2 w23 = *reinterpret_cast<const uint2*>(Qp + (size_t)(r0 + 8) * HD + d0);
        uint2 w45 = *reinterpret_cast<const uint2*>(Qp + (size_t)r0 * HD + d0 + 8);
        uint2 w67 = *reinterpret_cast<const uint2*>(Qp + (size_t)(r0 + 8) * HD + d0 + 8);
        qh[kk][0] = h2scale8(HI_PAIR(w01.x, w01.y)); ql[kk][0] = h2scale8(LO_PAIR(w01.x, w01.y));
        qh[kk][1] = h2scale8(HI_PAIR(w23.x, w23.y)); ql[kk][1] = h2scale8(LO_PAIR(w23.x, w23.y));
        qh[kk][2] = h2scale8(HI_PAIR(w45.x, w45.y)); ql[kk][2] = h2scale8(LO_PAIR(w45.x, w45.y));
        qh[kk][3] = h2scale8(HI_PAIR(w67.x, w67.y)); ql[kk][3] = h2scale8(LO_PAIR(w67.x, w67.y));
    }

    float oacc[8][4];
    #pragma unroll
    for (int t = 0; t < 8; t++)
        #pragma unroll
        for (int i = 0; i < 4; i++) oacc[t][i] = 0.f;
    float m0 = -1e30f, m1 = -1e30f, l0 = 0.f, l1 = 0.f;

    prefetch(0, 0);
    asm volatile("cp.async.commit_group;");
    prefetch(1, 1);
    asm volatile("cp.async.commit_group;");

    for (int c = 0; c < NCHUNK; c++) {
        asm volatile("cp.async.wait_group 1;");
        __syncthreads();
        if (c + 2 < NCHUNK) prefetch((c + 2) % 3, c + 2);
        asm volatile("cp.async.commit_group;");

        const uint32_t* Kh = dsm + (c % 3) * ATTN_STAGE_U32;
        const uint32_t* Kl = Kh + AK_U32;
        const uint32_t* Vh = Kh + 2 * AK_U32;
        const uint32_t* Vl = Vh + AV_U32;

        float sacc[8][4];
        #pragma unroll
        for (int t = 0; t < 8; t++)
            #pragma unroll
            for (int i = 0; i < 4; i++) sacc[t][i] = 0.f;

        #pragma unroll
        for (int kk = 0; kk < 4; kk++) {
            #pragma unroll
            for (int nt = 0; nt < 8; nt++) {
                int cidx = (nt * 8 + r0) * AK_LD + kk * 8 + (lane & 3);
                uint32_t bh[2], bl[2];
                bh[0] = Kh[cidx]; bh[1] = Kh[cidx + 4];
                bl[0] = Kl[cidx]; bl[1] = Kl[cidx + 4];
                mma3(sacc[nt], qh[kk], ql[kk], bh, bl);
            }
        }

        float mx0 = -1e30f, mx1 = -1e30f;
        #pragma unroll
        for (int t = 0; t < 8; t++) {
            mx0 = fmaxf(mx0, fmaxf(sacc[t][0], sacc[t][1]));
            mx1 = fmaxf(mx1, fmaxf(sacc[t][2], sacc[t][3]));
        }
        mx0 = fmaxf(mx0, __shfl_xor_sync(0xffffffffu, mx0, 1));
        mx0 = fmaxf(mx0, __shfl_xor_sync(0xffffffffu, mx0, 2));
        mx1 = fmaxf(mx1, __shfl_xor_sync(0xffffffffu, mx1, 1));
        mx1 = fmaxf(mx1, __shfl_xor_sync(0xffffffffu, mx1, 2));

        float mn0 = fmaxf(m0, mx0), mn1 = fmaxf(m1, mx1);
        float al0 = __expf(m0 - mn0), al1 = __expf(m1 - mn1);
        float s0 = 0.f, s1 = 0.f;
        #pragma unroll
        for (int t = 0; t < 8; t++) {
            sacc[t][0] = __expf(sacc[t][0] - mn0);
            sacc[t][1] = __expf(sacc[t][1] - mn0);
            sacc[t][2] = __expf(sacc[t][2] - mn1);
            sacc[t][3] = __expf(sacc[t][3] - mn1);
            s0 += sacc[t][0] + sacc[t][1];
            s1 += sacc[t][2] + sacc[t][3];
        }
        s0 += __shfl_xor_sync(0xffffffffu, s0, 1);
        s0 += __shfl_xor_sync(0xffffffffu, s0, 2);
        s1 += __shfl_xor_sync(0xffffffffu, s1, 1);
        s1 += __shfl_xor_sync(0xffffffffu, s1, 2);
        l0 = l0 * al0 + s0;
        l1 = l1 * al1 + s1;
        m0 = mn0; m1 = mn1;
        #pragma unroll
        for (int nt = 0; nt < 8; nt++) {
            oacc[nt][0] *= al0; oacc[nt][1] *= al0;
            oacc[nt][2] *= al1; oacc[nt][3] *= al1;
        }

        #pragma unroll
        for (int kk = 0; kk < 4; kk++) {
            uint32_t pah[4], pal[4];
            psplit2(sacc[2 * kk][0],     sacc[2 * kk][1],     pah[0], pal[0]);
            psplit2(sacc[2 * kk][2],     sacc[2 * kk][3],     pah[1], pal[1]);
            psplit2(sacc[2 * kk + 1][0], sacc[2 * kk + 1][1], pah[2], pal[2]);
            psplit2(sacc[2 * kk + 1][2], sacc[2 * kk + 1][3], pah[3], pal[3]);
            int gp = kk * 8 + (lane & 3);
            #pragma unroll
            for (int nt = 0; nt < 8; nt++) {
                int d = nt * 8 + r0;
                uint32_t bh[2], bl[2];
                bh[0] = Vh[gp * AV_LD + d]; bh[1] = Vh[(gp + 4) * AV_LD + d];
                bl[0] = Vl[gp * AV_LD + d]; bl[1] = Vl[(gp + 4) * AV_LD + d];
                mma3(oacc[nt], pah, pal, bh, bl);
            }
        }
    }

    float inv0 = 1.f / l0, inv1 = 1.f / l1;
    int h = pair >> 3, b = pair & 7;
    #pragma unroll
    for (int nt = 0; nt < 8; nt++) {
        int q = qt * 128 + warp * 16 + r0;
        int dp = h * 32 + nt * 4 + (lane & 3);
        uint32_t h0, l0u, h1, l1u;
        psplit2(oacc[nt][0] * inv0, oacc[nt][1] * inv0, h0, l0u);
        psplit2(oacc[nt][2] * inv1, oacc[nt][3] * inv1, h1, l1u);
        size_t o = ((size_t)(b * QDIM + q)) * (DIM / 2) + dp;
        g_Hdh[o] = h0; g_Hdl[o] = l0u;
        g_Hdh[o + 8 * (DIM / 2)] = h1; g_Hdl[o + 8 * (DIM / 2)] = l1u;
    }
}

extern "C" void kernel_launch(void* const* d_in, const int* in_sizes, int n_in,
                              void* d_out, int out_size)
{
    (void)in_sizes; (void)n_in; (void)out_size;
    const float* q  = (const float*)d_in[0];
    const float* Wq = (const float*)d_in[1];
    const float* Wk = (const float*)d_in[2];
    const float* Wv = (const float*)d_in[3];
    const float* Wo = (const float*)d_in[4];
    float* out = (float*)d_out;

    static bool attrs_set = false;
    if (!attrs_set) {
        cudaFuncSetAttribute(qkv_kernel,   cudaFuncAttributeMaxDynamicSharedMemorySize, QKV_SMEM);
        cudaFuncSetAttribute(attn_kernel,  cudaFuncAttributeMaxDynamicSharedMemorySize, ATTN_SMEM);
        cudaFuncSetAttribute(oproj_kernel, cudaFuncAttributeMaxDynamicSharedMemorySize, OP_SMEM);
        attrs_set = true;
    }

    splitx_kernel<<<16384, 256>>>(q);
    splitw_qkv_kernel<<<1536, 256>>>(Wq, Wk, Wv);
    splitw_o_kernel<<<512, 256>>>(Wo);
    qkv_kernel<<<dim3(8, 256), 256, QKV_SMEM>>>();
    attn_kernel<<<dim3(4, 64), 256, ATTN_SMEM>>>();
    oproj_kernel<<<dim3(8, 32), 256, OP_SMEM>>>(out);
}